// round 8
// baseline (speedup 1.0000x reference)
#include <cuda_runtime.h>
#include <cstdint>

#define NB 16
#define NT 2048
#define ND 512
#define NH 512
#define G3 1536
#define KD 1024

#define BM 128
#define BN 256
#define BK 16
#define KITER (KD / BK)      // 64
#define NSTAGE 4

// smem pitches (floats) chosen for conflict-free mma fragment loads
#define PKA 20               // A row-major [BM][PKA];  banks 20g+tig distinct
#define PNB 264              // B k-major  [BK][PNB];   264 % 32 == 8 -> distinct
#define A_EL (BM * PKA)      // 2560 floats / stage
#define B_EL (BK * PNB)      // 4224 floats / stage
#define A_BYTES (A_EL * 4)   // 10240
#define B_BYTES (B_EL * 4)   // 16896
#define B_OFF   (NSTAGE * A_BYTES)                 // 40960
#define SMEM_TOTAL (NSTAGE * (A_BYTES + B_BYTES))  // 108544

#define NC 16
#define CT (NT / NC)         // 128

// Scratch (__device__ globals; no allocation allowed)
__device__ float g_xp[(size_t)NB * (NT + 1) * ND];   // tf32-rounded, zero-padded x
__device__ float g_Wk[(size_t)KD * G3];              // tf32-rounded W, [kk][n]
__device__ float g_gates[(size_t)NB * NT * G3];      // post-activation gates
__device__ float g_carryA[(size_t)NB * NC * NH];
__device__ float g_carryB[(size_t)NB * NC * NH];
__device__ float g_cin[(size_t)NB * NC * NH];

// ---------------------------------------------------------------------------
__device__ __forceinline__ uint32_t s2u(const void* p) {
    uint32_t a;
    asm("{ .reg .u64 t; cvta.to.shared.u64 t, %1; cvt.u32.u64 %0, t; }"
        : "=r"(a) : "l"(p));
    return a;
}
__device__ __forceinline__ void cp16(uint32_t dst, const void* src) {
    asm volatile("cp.async.cg.shared.global [%0], [%1], 16;" :: "r"(dst), "l"(src));
}
__device__ __forceinline__ float tf32r(float v) {
    uint32_t o;
    asm("cvt.rna.tf32.f32 %0, %1;" : "=r"(o) : "f"(v));
    return __uint_as_float(o);
}
__device__ __forceinline__ void mma_tf32(float* c, const uint32_t* a,
                                         const uint32_t* b) {
    asm volatile(
        "mma.sync.aligned.m16n8k8.row.col.f32.tf32.tf32.f32 "
        "{%0,%1,%2,%3}, {%4,%5,%6,%7}, {%8,%9}, {%0,%1,%2,%3};"
        : "+f"(c[0]), "+f"(c[1]), "+f"(c[2]), "+f"(c[3])
        : "r"(a[0]), "r"(a[1]), "r"(a[2]), "r"(a[3]), "r"(b[0]), "r"(b[1]));
}

// ---------------------------------------------------------------------------
// Prep: g_xp[b][0]=0, g_xp[b][tt]=tf32(x[b][tt-1]); both conv taps are unit
// row shifts of one buffer. W repacked k-major via smem tile transpose.
// ---------------------------------------------------------------------------
__global__ void pad_x_kernel(const float4* __restrict__ x) {
    const int PB = (NT + 1) * ND / 4;
    int idx = blockIdx.x * blockDim.x + threadIdx.x;
    if (idx >= NB * PB) return;
    int b = idx / PB;
    int r = idx - b * PB;
    float4 v = make_float4(0.f, 0.f, 0.f, 0.f);
    if (r >= ND / 4) {
        v = x[(size_t)b * (NT * ND / 4) + r - ND / 4];
        v.x = tf32r(v.x); v.y = tf32r(v.y); v.z = tf32r(v.z); v.w = tf32r(v.w);
    }
    reinterpret_cast<float4*>(g_xp)[idx] = v;
}

// g_Wk[ki*512+d][n] = tf32(w[n][d][ki]); 32x32 smem tile transpose.
__global__ void transpose_wk_kernel(const float* __restrict__ w) {
    __shared__ float tile[32][33];
    const int kk0 = blockIdx.x * 32;         // kk tile (never crosses ki bound)
    const int n0  = blockIdx.y * 32;
    const int tx = threadIdx.x, ty = threadIdx.y;   // (32, 8)
    const int ki = kk0 >> 9;
#pragma unroll
    for (int r = 0; r < 4; r++) {
        const int n  = n0 + ty + r * 8;
        const int d  = (kk0 + tx) & 511;
        tile[ty + r * 8][tx] = w[(size_t)n * KD + d * 2 + ki];
    }
    __syncthreads();
#pragma unroll
    for (int r = 0; r < 4; r++) {
        const int kk = kk0 + ty + r * 8;
        g_Wk[(size_t)kk * G3 + n0 + tx] = tf32r(tile[tx][ty + r * 8]);
    }
}

// ---------------------------------------------------------------------------
// tf32 mma.sync GEMM: gates = act(A @ W + bias).
// CTA tile 128x256, 8 warps in 2(M) x 4(N), warp tile 64x64, mma m16n8k8.
// 4-stage cp.async pipeline (3 in flight).
// ---------------------------------------------------------------------------
__global__ __launch_bounds__(256, 1)
void gemm_mma_kernel(const float* __restrict__ bias) {
    extern __shared__ float sm[];
    const uint32_t sb = s2u(sm);
    const int tid = threadIdx.x;
    const int wid = tid >> 5, lid = tid & 31;
    const int wm = wid & 1, wn = wid >> 1;          // 2 x 4 warp grid
    const int g = lid >> 2, tig = lid & 3;

    const int n0 = blockIdx.x * BN;
    const int m0 = blockIdx.y * BM;
    const int b  = m0 >> 11;
    const int t0 = m0 & (NT - 1);

    float cf[4][8][4];
#pragma unroll
    for (int i = 0; i < 4; i++)
#pragma unroll
        for (int j = 0; j < 8; j++)
#pragma unroll
            for (int q = 0; q < 4; q++) cf[i][j][q] = 0.f;

    auto load_chunk = [&](int c, int s) {
        const int k0  = c * BK;
        const int tap = (k0 >= ND) ? 1 : 0;
        const int d0  = k0 & (ND - 1);
        const float* asrc = g_xp + ((size_t)(b * (NT + 1) + t0 + tap)) * ND + d0;
        const uint32_t adst = sb + s * A_BYTES;
#pragma unroll
        for (int i = 0; i < 2; i++) {                // 512 x 16B chunks
            int idx = tid + (i << 8);
            int r = idx >> 2, cc = (idx & 3) << 2;
            cp16(adst + (r * PKA + cc) * 4, asrc + (size_t)r * ND + cc);
        }
        const float* bsrc = g_Wk + (size_t)k0 * G3 + n0;
        const uint32_t bdst = sb + B_OFF + s * B_BYTES;
#pragma unroll
        for (int i = 0; i < 4; i++) {                // 1024 x 16B chunks
            int idx = tid + (i << 8);
            int r = idx >> 6, cc = (idx & 63) << 2;
            cp16(bdst + (r * PNB + cc) * 4, bsrc + (size_t)r * G3 + cc);
        }
    };

    // Prologue: fill 3 stages
#pragma unroll
    for (int c = 0; c < NSTAGE - 1; c++) {
        load_chunk(c, c);
        asm volatile("cp.async.commit_group;");
    }

    for (int c = 0; c < KITER; c++) {
        const int s = c & (NSTAGE - 1);
        asm volatile("cp.async.wait_group %0;" :: "n"(NSTAGE - 2));
        __syncthreads();

        const int cn = c + NSTAGE - 1;
        if (cn < KITER) load_chunk(cn, cn & (NSTAGE - 1));
        asm volatile("cp.async.commit_group;");

        const uint32_t* As = reinterpret_cast<const uint32_t*>(sm) + s * A_EL;
        const uint32_t* Bs = reinterpret_cast<const uint32_t*>(sm) +
                             (B_OFF >> 2) + s * B_EL;
#pragma unroll
        for (int k8 = 0; k8 < 2; k8++) {
            const int kk = k8 * 8;
            uint32_t af[4][4], bf[8][2];
#pragma unroll
            for (int i = 0; i < 4; i++) {
                const int base = (wm * 64 + i * 16 + g) * PKA + kk + tig;
                af[i][0] = As[base];
                af[i][1] = As[base + 8 * PKA];
                af[i][2] = As[base + 4];
                af[i][3] = As[base + 8 * PKA + 4];
            }
#pragma unroll
            for (int j = 0; j < 8; j++) {
                const int base = (kk + tig) * PNB + wn * 64 + j * 8 + g;
                bf[j][0] = Bs[base];
                bf[j][1] = Bs[base + 4 * PNB];
            }
#pragma unroll
            for (int i = 0; i < 4; i++)
#pragma unroll
                for (int j = 0; j < 8; j++) mma_tf32(cf[i][j], af[i], bf[j]);
        }
    }

    // Epilogue: bias + activation, direct store to g_gates.
#pragma unroll
    for (int j = 0; j < 8; j++) {
        const int col = n0 + wn * 64 + j * 8 + 2 * tig;
        const float b0 = bias[col], b1 = bias[col + 1];
        const bool is_z = col < NH;   // 64-col groups never straddle NH
#pragma unroll
        for (int i = 0; i < 4; i++) {
            const int r0 = m0 + wm * 64 + i * 16 + g;
#pragma unroll
            for (int h = 0; h < 2; h++) {
                float v0 = cf[i][j][2 * h]     + b0;
                float v1 = cf[i][j][2 * h + 1] + b1;
                float o0, o1;
                if (is_z) {
                    float e0 = __expf(2.f * v0), e1 = __expf(2.f * v1);
                    o0 = 1.f - __fdividef(2.f, e0 + 1.f);
                    o1 = 1.f - __fdividef(2.f, e1 + 1.f);
                } else {
                    o0 = __fdividef(1.f, 1.f + __expf(-v0));
                    o1 = __fdividef(1.f, 1.f + __expf(-v1));
                }
                *reinterpret_cast<float2*>(
                    g_gates + (size_t)(r0 + 8 * h) * G3 + col) =
                    make_float2(o0, o1);
            }
        }
    }
}

// ---------------------------------------------------------------------------
// fo-pool: chunked linear-recurrence scan. NC=16 chunks -> 131k threads.
// ---------------------------------------------------------------------------
__global__ __launch_bounds__(256)
void fo_carry_kernel() {
    const int idx   = blockIdx.x * blockDim.x + threadIdx.x;
    const int h     = idx & (NH - 1);
    const int chunk = (idx >> 9) & (NC - 1);
    const int b     = idx >> 13;

    const float* gp = g_gates + ((size_t)b * NT + (size_t)chunk * CT) * G3 + h;
    float A = 1.f, Bc = 0.f;
#pragma unroll 8
    for (int t = 0; t < CT; t++) {
        const float* gt = gp + (size_t)t * G3;
        const float z = gt[0];
        const float f = gt[NH];
        Bc = f * Bc + (1.f - f) * z;
        A *= f;
    }
    const size_t ci = ((size_t)b * NC + chunk) * NH + h;
    g_carryA[ci] = A;
    g_carryB[ci] = Bc;
}

__global__ __launch_bounds__(256)
void fo_carry_scan_kernel() {
    const int idx = blockIdx.x * blockDim.x + threadIdx.x;
    const int h = idx & (NH - 1);
    const int b = idx >> 9;
    float c = 0.f;
#pragma unroll
    for (int j = 0; j < NC; j++) {
        const size_t ci = ((size_t)b * NC + j) * NH + h;
        g_cin[ci] = c;
        c = g_carryA[ci] * c + g_carryB[ci];
    }
}

__global__ __launch_bounds__(256)
void fo_apply_kernel(float* __restrict__ out) {
    const int idx   = blockIdx.x * blockDim.x + threadIdx.x;
    const int h     = idx & (NH - 1);
    const int chunk = (idx >> 9) & (NC - 1);
    const int b     = idx >> 13;

    const float* gp = g_gates + ((size_t)b * NT + (size_t)chunk * CT) * G3 + h;
    float* Cp  = out + ((size_t)b * NT + (size_t)chunk * CT) * NH + h;
    float* OCp = Cp + (size_t)NB * NT * NH;

    float c = g_cin[((size_t)b * NC + chunk) * NH + h];
#pragma unroll 8
    for (int t = 0; t < CT; t++) {
        const float* gt = gp + (size_t)t * G3;
        const float z = gt[0];
        const float f = gt[NH];
        const float o = gt[2 * NH];
        c = f * c + (1.f - f) * z;
        Cp[(size_t)t * NH]  = c;
        OCp[(size_t)t * NH] = o * c;
    }
}

// ---------------------------------------------------------------------------
extern "C" void kernel_launch(void* const* d_in, const int* in_sizes, int n_in,
                              void* d_out, int out_size) {
    const float* x    = (const float*)d_in[0];   // [B, T, D]
    const float* w    = (const float*)d_in[1];   // [3H, D, 2]
    const float* bias = (const float*)d_in[2];   // [3H]
    float* out = (float*)d_out;                  // C then O*C

    const int padN = NB * (NT + 1) * ND / 4;
    pad_x_kernel<<<(padN + 255) / 256, 256>>>((const float4*)x);

    dim3 tg(KD / 32, G3 / 32);
    transpose_wk_kernel<<<tg, dim3(32, 8)>>>(w);

    cudaFuncSetAttribute(gemm_mma_kernel,
                         cudaFuncAttributeMaxDynamicSharedMemorySize, SMEM_TOTAL);
    dim3 grid(G3 / BN, (NB * NT) / BM);          // (6, 256)
    gemm_mma_kernel<<<grid, 256, SMEM_TOTAL>>>(bias);

    fo_carry_kernel<<<(NB * NC * NH) / 256, 256>>>();
    fo_carry_scan_kernel<<<(NB * NH) / 256, 256>>>();
    fo_apply_kernel<<<(NB * NC * NH) / 256, 256>>>(out);
}

// round 11
// speedup vs baseline: 1.1512x; 1.1512x over previous
#include <cuda_runtime.h>
#include <cstdint>

#define NB 16
#define NT 2048
#define ND 512
#define NH 512
#define G3 1536
#define KD 1024

#define BM 128
#define BN 128
#define BK 32
#define KITER (KD / BK)      // 32
#define NSTAGE 3

// smem pitches (floats) chosen for conflict-free mma fragment loads
#define PKA 36               // A row-major [BM][PKA]; banks (36g+tig)%32=4g+tig distinct
#define PNB 136              // B k-major  [BK][PNB]; 136%32==8 -> 8tig+g distinct
#define A_EL (BM * PKA)      // 4608 floats / stage
#define B_EL (BK * PNB)      // 4352 floats / stage
#define A_BYTES (A_EL * 4)   // 18432
#define B_BYTES (B_EL * 4)   // 17408
#define B_OFF   (NSTAGE * A_BYTES)                 // 55296
#define SMEM_TOTAL (NSTAGE * (A_BYTES + B_BYTES))  // 107520 (x2 CTAs = 215KB <= 227KB)

#define NC 32
#define CT (NT / NC)         // 64

// Scratch (__device__ globals; no allocation allowed)
__device__ float g_xp[(size_t)NB * (NT + 1) * ND];   // tf32-rounded, zero-padded x
__device__ float g_Wk[(size_t)KD * G3];              // tf32-rounded W, [kk][n]
__device__ float g_bias[G3];
__device__ float g_gates[(size_t)NB * NT * G3];      // post-activation gates
__device__ float g_carryA[(size_t)NB * NC * NH];
__device__ float g_carryB[(size_t)NB * NC * NH];
__device__ float g_cin[(size_t)NB * NC * NH];

// ---------------------------------------------------------------------------
__device__ __forceinline__ uint32_t s2u(const void* p) {
    uint32_t a;
    asm("{ .reg .u64 t; cvta.to.shared.u64 t, %1; cvt.u32.u64 %0, t; }"
        : "=r"(a) : "l"(p));
    return a;
}
__device__ __forceinline__ void cp16(uint32_t dst, const void* src) {
    asm volatile("cp.async.cg.shared.global [%0], [%1], 16;" :: "r"(dst), "l"(src));
}
__device__ __forceinline__ float tf32r(float v) {
    uint32_t o;
    asm("cvt.rna.tf32.f32 %0, %1;" : "=r"(o) : "f"(v));
    return __uint_as_float(o);
}
__device__ __forceinline__ void mma_tf32(float* c, const uint32_t* a,
                                         const uint32_t* b) {
    asm volatile(
        "mma.sync.aligned.m16n8k8.row.col.f32.tf32.tf32.f32 "
        "{%0,%1,%2,%3}, {%4,%5,%6,%7}, {%8,%9}, {%0,%1,%2,%3};"
        : "+f"(c[0]), "+f"(c[1]), "+f"(c[2]), "+f"(c[3])
        : "r"(a[0]), "r"(a[1]), "r"(a[2]), "r"(a[3]), "r"(b[0]), "r"(b[1]));
}

// ---------------------------------------------------------------------------
// Prep kernels
// ---------------------------------------------------------------------------
__global__ void pad_x_kernel(const float4* __restrict__ x) {
    const int PB = (NT + 1) * ND / 4;
    int idx = blockIdx.x * blockDim.x + threadIdx.x;
    if (idx >= NB * PB) return;
    int b = idx / PB;
    int r = idx - b * PB;
    float4 v = make_float4(0.f, 0.f, 0.f, 0.f);
    if (r >= ND / 4) {
        v = x[(size_t)b * (NT * ND / 4) + r - ND / 4];
        v.x = tf32r(v.x); v.y = tf32r(v.y); v.z = tf32r(v.z); v.w = tf32r(v.w);
    }
    reinterpret_cast<float4*>(g_xp)[idx] = v;
}

// g_Wk[ki*512+d][n] = tf32(w[n][d][ki]); 32x32 smem tile transpose.
__global__ void transpose_wk_kernel(const float* __restrict__ w) {
    __shared__ float tile[32][33];
    const int kk0 = blockIdx.x * 32;
    const int n0  = blockIdx.y * 32;
    const int tx = threadIdx.x, ty = threadIdx.y;   // (32, 8)
    const int ki = kk0 >> 9;
#pragma unroll
    for (int r = 0; r < 4; r++) {
        const int n  = n0 + ty + r * 8;
        const int d  = (kk0 + tx) & 511;
        tile[ty + r * 8][tx] = w[(size_t)n * KD + d * 2 + ki];
    }
    __syncthreads();
#pragma unroll
    for (int r = 0; r < 4; r++) {
        const int kk = kk0 + ty + r * 8;
        g_Wk[(size_t)kk * G3 + n0 + tx] = tf32r(tile[tx][ty + r * 8]);
    }
}

// Launch #3 (tiny): positions the GEMM as the 4th launch for ncu capture.
__global__ void bias_copy_kernel(const float* __restrict__ bias) {
    int i = blockIdx.x * blockDim.x + threadIdx.x;
    if (i < G3) g_bias[i] = bias[i];
}

// ---------------------------------------------------------------------------
// tf32 mma.sync GEMM: gates = act(A @ W + bias).
// CTA 128x128, 8 warps 2(M) x 4(N), warp tile 64x32, BK=32 (half the syncs),
// 3-stage cp.async pipeline (2 in flight).
// ---------------------------------------------------------------------------
__global__ __launch_bounds__(256, 2)
void gemm_mma_kernel() {
    extern __shared__ float sm[];
    const uint32_t sb = s2u(sm);
    const int tid = threadIdx.x;
    const int wid = tid >> 5, lid = tid & 31;
    const int wm = wid & 1, wn = wid >> 1;
    const int g = lid >> 2, tig = lid & 3;

    const int n0 = blockIdx.x * BN;
    const int m0 = blockIdx.y * BM;
    const int b  = m0 >> 11;
    const int t0 = m0 & (NT - 1);

    float cf[4][4][4];
#pragma unroll
    for (int i = 0; i < 4; i++)
#pragma unroll
        for (int j = 0; j < 4; j++)
#pragma unroll
            for (int q = 0; q < 4; q++) cf[i][j][q] = 0.f;

    auto load_chunk = [&](int c, int s) {
        const int k0  = c * BK;
        const int tap = (k0 >= ND) ? 1 : 0;
        const int d0  = k0 & (ND - 1);
        const float* asrc = g_xp + ((size_t)(b * (NT + 1) + t0 + tap)) * ND + d0;
        const uint32_t adst = sb + s * A_BYTES;
#pragma unroll
        for (int i = 0; i < 4; i++) {                // 1024 x 16B: A 128x32
            int idx = tid + (i << 8);
            int r = idx >> 3, cc = (idx & 7) << 2;
            cp16(adst + (r * PKA + cc) * 4, asrc + (size_t)r * ND + cc);
        }
        const float* bsrc = g_Wk + (size_t)k0 * G3 + n0;
        const uint32_t bdst = sb + B_OFF + s * B_BYTES;
#pragma unroll
        for (int i = 0; i < 4; i++) {                // 1024 x 16B: B 32x128
            int idx = tid + (i << 8);
            int r = idx >> 5, cc = (idx & 31) << 2;
            cp16(bdst + (r * PNB + cc) * 4, bsrc + (size_t)r * G3 + cc);
        }
    };

    // Prologue: fill 2 stages
#pragma unroll
    for (int c = 0; c < NSTAGE - 1; c++) {
        load_chunk(c, c);
        asm volatile("cp.async.commit_group;");
    }

    for (int c = 0; c < KITER; c++) {
        const int s = (c * 43691) & 0xFFFF, s3 = c % NSTAGE;  // (mod-3 via %, cheap)
        (void)s;
        asm volatile("cp.async.wait_group %0;" :: "n"(NSTAGE - 2));
        __syncthreads();

        const int cn = c + NSTAGE - 1;
        if (cn < KITER) load_chunk(cn, cn % NSTAGE);
        asm volatile("cp.async.commit_group;");

        const uint32_t* As = reinterpret_cast<const uint32_t*>(sm) + s3 * A_EL;
        const uint32_t* Bs = reinterpret_cast<const uint32_t*>(sm) +
                             (B_OFF >> 2) + s3 * B_EL;
#pragma unroll
        for (int k8 = 0; k8 < 4; k8++) {
            const int kk = k8 * 8;
            uint32_t af[4][4], bf[4][2];
#pragma unroll
            for (int i = 0; i < 4; i++) {
                const int base = (wm * 64 + i * 16 + g) * PKA + kk + tig;
                af[i][0] = As[base];
                af[i][1] = As[base + 8 * PKA];
                af[i][2] = As[base + 4];
                af[i][3] = As[base + 8 * PKA + 4];
            }
#pragma unroll
            for (int j = 0; j < 4; j++) {
                const int base = (kk + tig) * PNB + wn * 32 + j * 8 + g;
                bf[j][0] = Bs[base];
                bf[j][1] = Bs[base + 4 * PNB];
            }
#pragma unroll
            for (int i = 0; i < 4; i++)
#pragma unroll
                for (int j = 0; j < 4; j++) mma_tf32(cf[i][j], af[i], bf[j]);
        }
    }

    // Epilogue: bias + activation, direct store to g_gates.
#pragma unroll
    for (int j = 0; j < 4; j++) {
        const int col = n0 + wn * 32 + j * 8 + 2 * tig;
        const float b0 = g_bias[col], b1 = g_bias[col + 1];
        const bool is_z = col < NH;
#pragma unroll
        for (int i = 0; i < 4; i++) {
            const int r0 = m0 + wm * 64 + i * 16 + g;
#pragma unroll
            for (int h = 0; h < 2; h++) {
                float v0 = cf[i][j][2 * h]     + b0;
                float v1 = cf[i][j][2 * h + 1] + b1;
                float o0, o1;
                if (is_z) {
                    float e0 = __expf(2.f * v0), e1 = __expf(2.f * v1);
                    o0 = 1.f - __fdividef(2.f, e0 + 1.f);
                    o1 = 1.f - __fdividef(2.f, e1 + 1.f);
                } else {
                    o0 = __fdividef(1.f, 1.f + __expf(-v0));
                    o1 = __fdividef(1.f, 1.f + __expf(-v1));
                }
                *reinterpret_cast<float2*>(
                    g_gates + (size_t)(r0 + 8 * h) * G3 + col) =
                    make_float2(o0, o1);
            }
        }
    }
}

// ---------------------------------------------------------------------------
// fo-pool: chunked linear-recurrence scan. NC=32 chunks -> 262k threads.
// ---------------------------------------------------------------------------
__global__ __launch_bounds__(256)
void fo_carry_kernel() {
    const int idx   = blockIdx.x * blockDim.x + threadIdx.x;
    const int h     = idx & (NH - 1);
    const int chunk = (idx >> 9) & (NC - 1);
    const int b     = idx >> 14;

    const float* gp = g_gates + ((size_t)b * NT + (size_t)chunk * CT) * G3 + h;
    float A = 1.f, Bc = 0.f;
#pragma unroll 8
    for (int t = 0; t < CT; t++) {
        const float* gt = gp + (size_t)t * G3;
        const float z = gt[0];
        const float f = gt[NH];
        Bc = f * Bc + (1.f - f) * z;
        A *= f;
    }
    const size_t ci = ((size_t)b * NC + chunk) * NH + h;
    g_carryA[ci] = A;
    g_carryB[ci] = Bc;
}

__global__ __launch_bounds__(256)
void fo_carry_scan_kernel() {
    const int idx = blockIdx.x * blockDim.x + threadIdx.x;
    const int h = idx & (NH - 1);
    const int b = idx >> 9;
    float c = 0.f;
#pragma unroll
    for (int j = 0; j < NC; j++) {
        const size_t ci = ((size_t)b * NC + j) * NH + h;
        g_cin[ci] = c;
        c = g_carryA[ci] * c + g_carryB[ci];
    }
}

__global__ __launch_bounds__(256)
void fo_apply_kernel(float* __restrict__ out) {
    const int idx   = blockIdx.x * blockDim.x + threadIdx.x;
    const int h     = idx & (NH - 1);
    const int chunk = (idx >> 9) & (NC - 1);
    const int b     = idx >> 14;

    const float* gp = g_gates + ((size_t)b * NT + (size_t)chunk * CT) * G3 + h;
    float* Cp  = out + ((size_t)b * NT + (size_t)chunk * CT) * NH + h;
    float* OCp = Cp + (size_t)NB * NT * NH;

    float c = g_cin[((size_t)b * NC + chunk) * NH + h];
#pragma unroll 8
    for (int t = 0; t < CT; t++) {
        const float* gt = gp + (size_t)t * G3;
        const float z = gt[0];
        const float f = gt[NH];
        const float o = gt[2 * NH];
        c = f * c + (1.f - f) * z;
        Cp[(size_t)t * NH]  = c;
        OCp[(size_t)t * NH] = o * c;
    }
}

// ---------------------------------------------------------------------------
extern "C" void kernel_launch(void* const* d_in, const int* in_sizes, int n_in,
                              void* d_out, int out_size) {
    const float* x    = (const float*)d_in[0];   // [B, T, D]
    const float* w    = (const float*)d_in[1];   // [3H, D, 2]
    const float* bias = (const float*)d_in[2];   // [3H]
    float* out = (float*)d_out;                  // C then O*C

    const int padN = NB * (NT + 1) * ND / 4;
    pad_x_kernel<<<(padN + 255) / 256, 256>>>((const float4*)x);   // launch 1

    dim3 tg(KD / 32, G3 / 32);
    transpose_wk_kernel<<<tg, dim3(32, 8)>>>(w);                   // launch 2

    bias_copy_kernel<<<G3 / 256, 256>>>(bias);                     // launch 3 (tiny)

    cudaFuncSetAttribute(gemm_mma_kernel,
                         cudaFuncAttributeMaxDynamicSharedMemorySize, SMEM_TOTAL);
    dim3 grid(G3 / BN, (NB * NT) / BM);          // (12, 256)
    gemm_mma_kernel<<<grid, 256, SMEM_TOTAL>>>();                  // launch 4 <- ncu

    fo_carry_kernel<<<(NB * NC * NH) / 256, 256>>>();
    fo_carry_scan_kernel<<<(NB * NH) / 256, 256>>>();
    fo_apply_kernel<<<(NB * NC * NH) / 256, 256>>>(out);
}

// round 12
// speedup vs baseline: 1.1955x; 1.0385x over previous
#include <cuda_runtime.h>
#include <cstdint>

#define NB 16
#define NT 2048
#define ND 512
#define NH 512
#define G3 1536
#define KD 1024

#define BM 128
#define BN 128
#define BK 32
#define KITER (KD / BK)      // 32
#define NSTAGE 3

// smem pitches (floats) chosen for conflict-free mma fragment loads
#define PKA 36               // A row-major [BM][PKA]; banks (36g+tig)%32=4g+tig distinct
#define PNB 136              // B k-major  [BK][PNB]; 136%32==8 -> 8tig+g distinct
#define A_EL (BM * PKA)      // 4608 floats / stage
#define B_EL (BK * PNB)      // 4352 floats / stage
#define A_BYTES (A_EL * 4)   // 18432
#define B_BYTES (B_EL * 4)   // 17408
#define B_OFF   (NSTAGE * A_BYTES)                 // 55296
#define SMEM_TOTAL (NSTAGE * (A_BYTES + B_BYTES))  // 107520 (x2 CTAs = 215KB <= 227KB)

#define NC 32
#define CT (NT / NC)         // 64

// Scratch (__device__ globals; no allocation allowed)
__device__ float g_xp[(size_t)NB * (NT + 1) * ND];   // tf32-rounded, zero-padded x
__device__ float g_Wk[(size_t)KD * G3];              // tf32-rounded W, [kk][n]
__device__ float g_bias[G3];
__device__ float g_gates[(size_t)NB * NT * G3];      // post-activation gates
__device__ float g_carryA[(size_t)NB * NC * NH];
__device__ float g_carryB[(size_t)NB * NC * NH];
__device__ float g_cin[(size_t)NB * NC * NH];

// ---------------------------------------------------------------------------
__device__ __forceinline__ uint32_t s2u(const void* p) {
    uint32_t a;
    asm("{ .reg .u64 t; cvta.to.shared.u64 t, %1; cvt.u32.u64 %0, t; }"
        : "=r"(a) : "l"(p));
    return a;
}
__device__ __forceinline__ void cp16(uint32_t dst, const void* src) {
    asm volatile("cp.async.cg.shared.global [%0], [%1], 16;" :: "r"(dst), "l"(src));
}
__device__ __forceinline__ float tf32r(float v) {
    uint32_t o;
    asm("cvt.rna.tf32.f32 %0, %1;" : "=r"(o) : "f"(v));
    return __uint_as_float(o);
}
__device__ __forceinline__ void mma_tf32(float* c, const uint32_t* a,
                                         const uint32_t* b) {
    asm volatile(
        "mma.sync.aligned.m16n8k8.row.col.f32.tf32.tf32.f32 "
        "{%0,%1,%2,%3}, {%4,%5,%6,%7}, {%8,%9}, {%0,%1,%2,%3};"
        : "+f"(c[0]), "+f"(c[1]), "+f"(c[2]), "+f"(c[3])
        : "r"(a[0]), "r"(a[1]), "r"(a[2]), "r"(a[3]), "r"(b[0]), "r"(b[1]));
}

// ---------------------------------------------------------------------------
// Prep kernels
// ---------------------------------------------------------------------------
__global__ void pad_x_kernel(const float4* __restrict__ x) {
    const int PB = (NT + 1) * ND / 4;
    int idx = blockIdx.x * blockDim.x + threadIdx.x;
    if (idx >= NB * PB) return;
    int b = idx / PB;
    int r = idx - b * PB;
    float4 v = make_float4(0.f, 0.f, 0.f, 0.f);
    if (r >= ND / 4) {
        v = x[(size_t)b * (NT * ND / 4) + r - ND / 4];
        v.x = tf32r(v.x); v.y = tf32r(v.y); v.z = tf32r(v.z); v.w = tf32r(v.w);
    }
    reinterpret_cast<float4*>(g_xp)[idx] = v;
}

// g_Wk[ki*512+d][n] = tf32(w[n][d][ki]); 32x32 smem tile transpose.
__global__ void transpose_wk_kernel(const float* __restrict__ w) {
    __shared__ float tile[32][33];
    const int kk0 = blockIdx.x * 32;
    const int n0  = blockIdx.y * 32;
    const int tx = threadIdx.x, ty = threadIdx.y;   // (32, 8)
    const int ki = kk0 >> 9;
#pragma unroll
    for (int r = 0; r < 4; r++) {
        const int n  = n0 + ty + r * 8;
        const int d  = (kk0 + tx) & 511;
        tile[ty + r * 8][tx] = w[(size_t)n * KD + d * 2 + ki];
    }
    __syncthreads();
#pragma unroll
    for (int r = 0; r < 4; r++) {
        const int kk = kk0 + ty + r * 8;
        g_Wk[(size_t)kk * G3 + n0 + tx] = tf32r(tile[tx][ty + r * 8]);
    }
}

// Launch #3 (tiny): positions the GEMM as the 4th launch for ncu capture.
__global__ void bias_copy_kernel(const float* __restrict__ bias) {
    int i = blockIdx.x * blockDim.x + threadIdx.x;
    if (i < G3) g_bias[i] = bias[i];
}

// ---------------------------------------------------------------------------
// tf32 mma.sync GEMM: gates = act(A @ W + bias).
// CTA 128x128, 8 warps 2(M) x 4(N), warp tile 64x32, BK=32, 3-stage cp.async.
// Fragment registers double-buffered across k8 steps so LDS(k8+1) overlaps
// mma(k8) — breaks the per-chunk LDS-burst / HMMA-burst serialization.
// ---------------------------------------------------------------------------
__global__ __launch_bounds__(256, 2)
void gemm_mma_kernel() {
    extern __shared__ float sm[];
    const uint32_t sb = s2u(sm);
    const int tid = threadIdx.x;
    const int wid = tid >> 5, lid = tid & 31;
    const int wm = wid & 1, wn = wid >> 1;
    const int g = lid >> 2, tig = lid & 3;

    const int n0 = blockIdx.x * BN;
    const int m0 = blockIdx.y * BM;
    const int b  = m0 >> 11;
    const int t0 = m0 & (NT - 1);

    // per-thread invariant fragment offsets (address = base + imm)
    const int aoff = (wm * 64 + g) * PKA + tig;
    const int boff = tig * PNB + wn * 32 + g;

    float cf[4][4][4];
#pragma unroll
    for (int i = 0; i < 4; i++)
#pragma unroll
        for (int j = 0; j < 4; j++)
#pragma unroll
            for (int q = 0; q < 4; q++) cf[i][j][q] = 0.f;

    uint32_t af[2][4][4], bf[2][4][2];

    auto load_chunk = [&](int c, int s) {
        const int k0  = c * BK;
        const int tap = (k0 >= ND) ? 1 : 0;
        const int d0  = k0 & (ND - 1);
        const float* asrc = g_xp + ((size_t)(b * (NT + 1) + t0 + tap)) * ND + d0;
        const uint32_t adst = sb + s * A_BYTES;
#pragma unroll
        for (int i = 0; i < 4; i++) {                // 1024 x 16B: A 128x32
            int idx = tid + (i << 8);
            int r = idx >> 3, cc = (idx & 7) << 2;
            cp16(adst + (r * PKA + cc) * 4, asrc + (size_t)r * ND + cc);
        }
        const float* bsrc = g_Wk + (size_t)k0 * G3 + n0;
        const uint32_t bdst = sb + B_OFF + s * B_BYTES;
#pragma unroll
        for (int i = 0; i < 4; i++) {                // 1024 x 16B: B 32x128
            int idx = tid + (i << 8);
            int r = idx >> 5, cc = (idx & 31) << 2;
            cp16(bdst + (r * PNB + cc) * 4, bsrc + (size_t)r * G3 + cc);
        }
    };

    // Prologue: fill 2 stages
#pragma unroll
    for (int c = 0; c < NSTAGE - 1; c++) {
        load_chunk(c, c);
        asm volatile("cp.async.commit_group;");
    }

    for (int c = 0; c < KITER; c++) {
        const int s3 = c % NSTAGE;
        asm volatile("cp.async.wait_group %0;" :: "n"(NSTAGE - 2));
        __syncthreads();

        const uint32_t* As = reinterpret_cast<const uint32_t*>(sm) + s3 * A_EL;
        const uint32_t* Bs = reinterpret_cast<const uint32_t*>(sm) +
                             (B_OFF >> 2) + s3 * B_EL;

        // k8=0 fragments into buffer 0
#pragma unroll
        for (int i = 0; i < 4; i++) {
            const int base = aoff + i * 16 * PKA;
            af[0][i][0] = As[base];
            af[0][i][1] = As[base + 8 * PKA];
            af[0][i][2] = As[base + 4];
            af[0][i][3] = As[base + 8 * PKA + 4];
        }
#pragma unroll
        for (int j = 0; j < 4; j++) {
            const int base = boff + j * 8;
            bf[0][j][0] = Bs[base];
            bf[0][j][1] = Bs[base + 4 * PNB];
        }

        // issue next chunk's cp.asyncs inside the k8=0 LDS latency window
        const int cn = c + NSTAGE - 1;
        if (cn < KITER) load_chunk(cn, cn % NSTAGE);
        asm volatile("cp.async.commit_group;");

#pragma unroll
        for (int k8 = 0; k8 < 4; k8++) {
            const int cur = k8 & 1, nxt = cur ^ 1;
            if (k8 < 3) {                       // prefetch k8+1 fragments
                const int kk = (k8 + 1) * 8;
#pragma unroll
                for (int i = 0; i < 4; i++) {
                    const int base = aoff + i * 16 * PKA + kk;
                    af[nxt][i][0] = As[base];
                    af[nxt][i][1] = As[base + 8 * PKA];
                    af[nxt][i][2] = As[base + 4];
                    af[nxt][i][3] = As[base + 8 * PKA + 4];
                }
#pragma unroll
                for (int j = 0; j < 4; j++) {
                    const int base = boff + kk * PNB + j * 8;
                    bf[nxt][j][0] = Bs[base];
                    bf[nxt][j][1] = Bs[base + 4 * PNB];
                }
            }
#pragma unroll
            for (int i = 0; i < 4; i++)
#pragma unroll
                for (int j = 0; j < 4; j++)
                    mma_tf32(cf[i][j], af[cur][i], bf[cur][j]);
        }
    }

    // Epilogue: bias + activation, direct store to g_gates.
#pragma unroll
    for (int j = 0; j < 4; j++) {
        const int col = n0 + wn * 32 + j * 8 + 2 * tig;
        const float b0 = g_bias[col], b1 = g_bias[col + 1];
        const bool is_z = col < NH;
#pragma unroll
        for (int i = 0; i < 4; i++) {
            const int r0 = m0 + wm * 64 + i * 16 + g;
#pragma unroll
            for (int h = 0; h < 2; h++) {
                float v0 = cf[i][j][2 * h]     + b0;
                float v1 = cf[i][j][2 * h + 1] + b1;
                float o0, o1;
                if (is_z) {
                    float e0 = __expf(2.f * v0), e1 = __expf(2.f * v1);
                    o0 = 1.f - __fdividef(2.f, e0 + 1.f);
                    o1 = 1.f - __fdividef(2.f, e1 + 1.f);
                } else {
                    o0 = __fdividef(1.f, 1.f + __expf(-v0));
                    o1 = __fdividef(1.f, 1.f + __expf(-v1));
                }
                *reinterpret_cast<float2*>(
                    g_gates + (size_t)(r0 + 8 * h) * G3 + col) =
                    make_float2(o0, o1);
            }
        }
    }
}

// ---------------------------------------------------------------------------
// fo-pool: chunked linear-recurrence scan. NC=32 chunks -> 262k threads.
// ---------------------------------------------------------------------------
__global__ __launch_bounds__(256)
void fo_carry_kernel() {
    const int idx   = blockIdx.x * blockDim.x + threadIdx.x;
    const int h     = idx & (NH - 1);
    const int chunk = (idx >> 9) & (NC - 1);
    const int b     = idx >> 14;

    const float* gp = g_gates + ((size_t)b * NT + (size_t)chunk * CT) * G3 + h;
    float A = 1.f, Bc = 0.f;
#pragma unroll 8
    for (int t = 0; t < CT; t++) {
        const float* gt = gp + (size_t)t * G3;
        const float z = gt[0];
        const float f = gt[NH];
        Bc = f * Bc + (1.f - f) * z;
        A *= f;
    }
    const size_t ci = ((size_t)b * NC + chunk) * NH + h;
    g_carryA[ci] = A;
    g_carryB[ci] = Bc;
}

__global__ __launch_bounds__(256)
void fo_carry_scan_kernel() {
    const int idx = blockIdx.x * blockDim.x + threadIdx.x;
    const int h = idx & (NH - 1);
    const int b = idx >> 9;
    float c = 0.f;
#pragma unroll
    for (int j = 0; j < NC; j++) {
        const size_t ci = ((size_t)b * NC + j) * NH + h;
        g_cin[ci] = c;
        c = g_carryA[ci] * c + g_carryB[ci];
    }
}

__global__ __launch_bounds__(256)
void fo_apply_kernel(float* __restrict__ out) {
    const int idx   = blockIdx.x * blockDim.x + threadIdx.x;
    const int h     = idx & (NH - 1);
    const int chunk = (idx >> 9) & (NC - 1);
    const int b     = idx >> 14;

    const float* gp = g_gates + ((size_t)b * NT + (size_t)chunk * CT) * G3 + h;
    float* Cp  = out + ((size_t)b * NT + (size_t)chunk * CT) * NH + h;
    float* OCp = Cp + (size_t)NB * NT * NH;

    float c = g_cin[((size_t)b * NC + chunk) * NH + h];
#pragma unroll 8
    for (int t = 0; t < CT; t++) {
        const float* gt = gp + (size_t)t * G3;
        const float z = gt[0];
        const float f = gt[NH];
        const float o = gt[2 * NH];
        c = f * c + (1.f - f) * z;
        Cp[(size_t)t * NH]  = c;
        OCp[(size_t)t * NH] = o * c;
    }
}

// ---------------------------------------------------------------------------
extern "C" void kernel_launch(void* const* d_in, const int* in_sizes, int n_in,
                              void* d_out, int out_size) {
    const float* x    = (const float*)d_in[0];   // [B, T, D]
    const float* w    = (const float*)d_in[1];   // [3H, D, 2]
    const float* bias = (const float*)d_in[2];   // [3H]
    float* out = (float*)d_out;                  // C then O*C

    const int padN = NB * (NT + 1) * ND / 4;
    pad_x_kernel<<<(padN + 255) / 256, 256>>>((const float4*)x);   // launch 1

    dim3 tg(KD / 32, G3 / 32);
    transpose_wk_kernel<<<tg, dim3(32, 8)>>>(w);                   // launch 2

    bias_copy_kernel<<<G3 / 256, 256>>>(bias);                     // launch 3 (tiny)

    cudaFuncSetAttribute(gemm_mma_kernel,
                         cudaFuncAttributeMaxDynamicSharedMemorySize, SMEM_TOTAL);
    dim3 grid(G3 / BN, (NB * NT) / BM);          // (12, 256)
    gemm_mma_kernel<<<grid, 256, SMEM_TOTAL>>>();                  // launch 4 <- ncu

    fo_carry_kernel<<<(NB * NC * NH) / 256, 256>>>();
    fo_carry_scan_kernel<<<(NB * NH) / 256, 256>>>();
    fo_apply_kernel<<<(NB * NC * NH) / 256, 256>>>(out);
}

// round 15
// speedup vs baseline: 1.1989x; 1.0028x over previous
#include <cuda_runtime.h>
#include <cstdint>

#define NB 16
#define NT 2048
#define ND 512
#define NH 512
#define G3 1536
#define KD 1024

#define BM 128
#define BN 128
#define BK 32
#define KITER (KD / BK)      // 32
#define NSTAGE 3

// A: row-major [BM][PKA], k-pair interleaved columns; pitch 40 floats ->
//    LDS.64 banks (8g+2tig) mod 32 distinct per 16-lane phase.
#define PKA 40
#define A_EL (BM * PKA)          // 5120 floats
#define A_BYTES (A_EL * 4)       // 20480
// B: per chunk 4 k8-groups x 4 pair-rows x 264 floats (256 data + 8 pad)
//    LDS.64 banks (8tig+2g) mod 32 distinct per phase.
#define PNB 264
#define B_EL (16 * PNB)          // 4224 floats
#define B_BYTES (B_EL * 4)       // 16896
#define B_OFF   (NSTAGE * A_BYTES)                 // 61440
#define SMEM_TOTAL (NSTAGE * (A_BYTES + B_BYTES))  // 112128 (x2 = 219KB)

#define NC 32
#define CT (NT / NC)         // 64

// Scratch (__device__ globals; no allocation allowed)
__device__ float g_xp[(size_t)NB * (NT + 1) * ND];   // tf32, padded, k-pair-interleaved cols
__device__ float g_Wk[(size_t)KD * G3];              // tf32 W, [group][pair][n][2] layout
__device__ float g_bias[G3];
__device__ float g_gates[(size_t)NB * NT * G3];      // post-activation gates
__device__ float g_carryA[(size_t)NB * NC * NH];
__device__ float g_carryB[(size_t)NB * NC * NH];
__device__ float g_cin[(size_t)NB * NC * NH];

// ---------------------------------------------------------------------------
__device__ __forceinline__ uint32_t s2u(const void* p) {
    uint32_t a;
    asm("{ .reg .u64 t; cvta.to.shared.u64 t, %1; cvt.u32.u64 %0, t; }"
        : "=r"(a) : "l"(p));
    return a;
}
__device__ __forceinline__ void cp16(uint32_t dst, const void* src) {
    asm volatile("cp.async.cg.shared.global [%0], [%1], 16;" :: "r"(dst), "l"(src));
}
__device__ __forceinline__ float tf32r(float v) {
    uint32_t o;
    asm("cvt.rna.tf32.f32 %0, %1;" : "=r"(o) : "f"(v));
    return __uint_as_float(o);
}
__device__ __forceinline__ void lds64(uint32_t& r0, uint32_t& r1, uint32_t a) {
    asm volatile("ld.shared.v2.b32 {%0, %1}, [%2];" : "=r"(r0), "=r"(r1) : "r"(a));
}
__device__ __forceinline__ void mma_tf32(float* c, const uint32_t* a,
                                         const uint32_t* b) {
    asm volatile(
        "mma.sync.aligned.m16n8k8.row.col.f32.tf32.tf32.f32 "
        "{%0,%1,%2,%3}, {%4,%5,%6,%7}, {%8,%9}, {%0,%1,%2,%3};"
        : "+f"(c[0]), "+f"(c[1]), "+f"(c[2]), "+f"(c[3])
        : "r"(a[0]), "r"(a[1]), "r"(a[2]), "r"(a[3]), "r"(b[0]), "r"(b[1]));
}

// ---------------------------------------------------------------------------
// Prep kernels
// ---------------------------------------------------------------------------
// g_xp[b][0]=0; g_xp[b][tt] = tf32(x[b][tt-1]) with columns pair-interleaved
// within each 8-group: out float2 at col 8*gb+2i holds (src col 8gb+i, 8gb+i+4).
__global__ void pad_x_kernel(const float* __restrict__ x) {
    const int PPB = (NT + 1) * (ND / 2);     // float2 per batch
    int idx = blockIdx.x * blockDim.x + threadIdx.x;
    if (idx >= NB * PPB) return;
    int b  = idx / PPB;
    int r  = idx - b * PPB;
    int tt = r / (ND / 2);
    int p  = r - tt * (ND / 2);              // 0..255
    int gb = p >> 2, i = p & 3;
    float2 v = make_float2(0.f, 0.f);
    if (tt > 0) {
        const float* src = x + ((size_t)b * NT + (tt - 1)) * ND + gb * 8 + i;
        v.x = tf32r(src[0]);
        v.y = tf32r(src[4]);
    }
    *reinterpret_cast<float2*>(
        g_xp + ((size_t)b * (NT + 1) + tt) * ND + gb * 8 + 2 * i) = v;
}

// g_Wk layout: [kgroup(128)][pair(4)][n(G3)][sub(2)], where kk = 8*kgroup + pair
// (sub=0) or + pair + 4 (sub=1). Same k-pair interleave as A.
__global__ void transpose_wk_kernel(const float* __restrict__ w) {
    __shared__ float tile[32][33];
    const int kk0 = blockIdx.x * 32;
    const int n0  = blockIdx.y * 32;
    const int tx = threadIdx.x, ty = threadIdx.y;   // (32, 8)
    const int ki = kk0 >> 9;
#pragma unroll
    for (int r = 0; r < 4; r++) {
        const int n  = n0 + ty + r * 8;
        const int d  = (kk0 + tx) & 511;
        tile[ty + r * 8][tx] = w[(size_t)n * KD + d * 2 + ki];
    }
    __syncthreads();
#pragma unroll
    for (int r = 0; r < 4; r++) {
        const int kk = kk0 + ty + r * 8;
        const int n  = n0 + tx;
        const size_t dst =
            (((size_t)((kk >> 3) * 4 + (kk & 3)) * G3) + n) * 2 + ((kk >> 2) & 1);
        g_Wk[dst] = tf32r(tile[tx][ty + r * 8]);
    }
}

// Launch #3 (tiny): positions the GEMM as the 4th launch for ncu capture.
__global__ void bias_copy_kernel(const float* __restrict__ bias) {
    int i = blockIdx.x * blockDim.x + threadIdx.x;
    if (i < G3) g_bias[i] = bias[i];
}

// ---------------------------------------------------------------------------
// tf32 mma.sync GEMM. CTA 128x128, 8 warps 2(M)x4(N), warp tile 64x32, BK=32,
// 3-stage cp.async with register-rotated stage pointers (no runtime %), and
// LDS.64 fragment loads (k-pair interleaved) double-buffered across k8.
// ---------------------------------------------------------------------------
__global__ __launch_bounds__(256, 2)
void gemm_mma_kernel() {
    extern __shared__ float sm[];
    const uint32_t sb = s2u(sm);
    const int tid = threadIdx.x;
    const int wid = tid >> 5, lid = tid & 31;
    const int wm = wid & 1, wn = wid >> 1;
    const int g = lid >> 2, tig = lid & 3;

    const int n0 = blockIdx.x * BN;
    const int m0 = blockIdx.y * BM;
    const int b  = m0 >> 11;
    const int t0 = m0 & (NT - 1);

    // thread-invariant fragment byte offsets within a stage
    const uint32_t aoff = ((wm * 64 + g) * PKA + 2 * tig) * 4;
    const uint32_t boff = (tig * PNB + (wn * 32 + g) * 2) * 4;

    // rotating stage bases: consume (cA?,cB?) stage X; load into stage Z
    uint32_t lA0 = sb, lA1 = sb + A_BYTES, lA2 = sb + 2 * A_BYTES;
    uint32_t lB0 = sb + B_OFF, lB1 = lB0 + B_BYTES, lB2 = lB0 + 2 * B_BYTES;

    float cf[4][4][4];
#pragma unroll
    for (int i = 0; i < 4; i++)
#pragma unroll
        for (int j = 0; j < 4; j++)
#pragma unroll
            for (int q = 0; q < 4; q++) cf[i][j][q] = 0.f;

    uint32_t af[2][4][4], bf[2][4][2];

    auto load_chunk = [&](int c, uint32_t adst, uint32_t bdst) {
        const int k0  = c * BK;
        const int tap = (k0 >= ND) ? 1 : 0;
        const int d0  = k0 & (ND - 1);
        const float* asrc = g_xp + ((size_t)(b * (NT + 1) + t0 + tap)) * ND + d0;
#pragma unroll
        for (int i = 0; i < 4; i++) {            // A 128x32 floats
            int idx = tid + (i << 8);
            int r = idx >> 3, cc = (idx & 7) << 2;
            cp16(adst + (r * PKA + cc) * 4, asrc + (size_t)r * ND + cc);
        }
        // B: 16 pair-rows of 256 floats from g_Wk rows (c*16 + r)
        const float* bsrc = g_Wk + (size_t)(c * 16) * (G3 * 2) + n0 * 2;
#pragma unroll
        for (int i = 0; i < 4; i++) {
            int idx = tid + (i << 8);
            int r = idx >> 6, cc = (idx & 63) << 2;
            cp16(bdst + (r * PNB + cc) * 4, bsrc + (size_t)r * (G3 * 2) + cc);
        }
    };

    // Prologue: chunks 0,1 into stages 0,1
    load_chunk(0, lA0, lB0);
    asm volatile("cp.async.commit_group;");
    load_chunk(1, lA1, lB1);
    asm volatile("cp.async.commit_group;");

    for (int c = 0; c < KITER; c++) {
        asm volatile("cp.async.wait_group %0;" :: "n"(NSTAGE - 2));
        __syncthreads();

        const uint32_t Af = lA0 + aoff;          // consume stage
        const uint32_t Bf = lB0 + boff;

        // k8=0 fragments into buffer 0  (LDS.64 each)
#pragma unroll
        for (int i = 0; i < 4; i++) {
            const uint32_t base = Af + i * (16 * PKA * 4);
            lds64(af[0][i][0], af[0][i][2], base);
            lds64(af[0][i][1], af[0][i][3], base + 8 * PKA * 4);
        }
#pragma unroll
        for (int j = 0; j < 4; j++)
            lds64(bf[0][j][0], bf[0][j][1], Bf + j * 64);

        // next chunk's cp.asyncs inside the k8=0 LDS latency window
        const int cn = c + NSTAGE - 1;
        if (cn < KITER) load_chunk(cn, lA2, lB2);
        asm volatile("cp.async.commit_group;");

#pragma unroll
        for (int k8 = 0; k8 < 4; k8++) {
            const int cur = k8 & 1, nxt = cur ^ 1;
            if (k8 < 3) {                        // prefetch k8+1 fragments
                const uint32_t Afk = Af + (k8 + 1) * 32;         // 8 floats
                const uint32_t Bfk = Bf + (k8 + 1) * (4 * PNB * 4);
#pragma unroll
                for (int i = 0; i < 4; i++) {
                    const uint32_t base = Afk + i * (16 * PKA * 4);
                    lds64(af[nxt][i][0], af[nxt][i][2], base);
                    lds64(af[nxt][i][1], af[nxt][i][3], base + 8 * PKA * 4);
                }
#pragma unroll
                for (int j = 0; j < 4; j++)
                    lds64(bf[nxt][j][0], bf[nxt][j][1], Bfk + j * 64);
            }
#pragma unroll
            for (int i = 0; i < 4; i++)
#pragma unroll
                for (int j = 0; j < 4; j++)
                    mma_tf32(cf[i][j], af[cur][i], bf[cur][j]);
        }

        // rotate stages: consume->tail, next->consume, load->next
        uint32_t t;
        t = lA0; lA0 = lA1; lA1 = lA2; lA2 = t;
        t = lB0; lB0 = lB1; lB1 = lB2; lB2 = t;
    }

    // Epilogue: bias + activation, direct store to g_gates.
#pragma unroll
    for (int j = 0; j < 4; j++) {
        const int col = n0 + wn * 32 + j * 8 + 2 * tig;
        const float b0 = g_bias[col], b1 = g_bias[col + 1];
        const bool is_z = col < NH;
#pragma unroll
        for (int i = 0; i < 4; i++) {
            const int r0 = m0 + wm * 64 + i * 16 + g;
#pragma unroll
            for (int h = 0; h < 2; h++) {
                float v0 = cf[i][j][2 * h]     + b0;
                float v1 = cf[i][j][2 * h + 1] + b1;
                float o0, o1;
                if (is_z) {
                    float e0 = __expf(2.f * v0), e1 = __expf(2.f * v1);
                    o0 = 1.f - __fdividef(2.f, e0 + 1.f);
                    o1 = 1.f - __fdividef(2.f, e1 + 1.f);
                } else {
                    o0 = __fdividef(1.f, 1.f + __expf(-v0));
                    o1 = __fdividef(1.f, 1.f + __expf(-v1));
                }
                *reinterpret_cast<float2*>(
                    g_gates + (size_t)(r0 + 8 * h) * G3 + col) =
                    make_float2(o0, o1);
            }
        }
    }
}

// ---------------------------------------------------------------------------
// fo-pool: chunked linear-recurrence scan. NC=32 chunks -> 262k threads.
// ---------------------------------------------------------------------------
__global__ __launch_bounds__(256)
void fo_carry_kernel() {
    const int idx   = blockIdx.x * blockDim.x + threadIdx.x;
    const int h     = idx & (NH - 1);
    const int chunk = (idx >> 9) & (NC - 1);
    const int b     = idx >> 14;

    const float* gp = g_gates + ((size_t)b * NT + (size_t)chunk * CT) * G3 + h;
    float A = 1.f, Bc = 0.f;
#pragma unroll 8
    for (int t = 0; t < CT; t++) {
        const float* gt = gp + (size_t)t * G3;
        const float z = gt[0];
        const float f = gt[NH];
        Bc = f * Bc + (1.f - f) * z;
        A *= f;
    }
    const size_t ci = ((size_t)b * NC + chunk) * NH + h;
    g_carryA[ci] = A;
    g_carryB[ci] = Bc;
}

__global__ __launch_bounds__(256)
void fo_carry_scan_kernel() {
    const int idx = blockIdx.x * blockDim.x + threadIdx.x;
    const int h = idx & (NH - 1);
    const int b = idx >> 9;
    float c = 0.f;
#pragma unroll
    for (int j = 0; j < NC; j++) {
        const size_t ci = ((size_t)b * NC + j) * NH + h;
        g_cin[ci] = c;
        c = g_carryA[ci] * c + g_carryB[ci];
    }
}

__global__ __launch_bounds__(256)
void fo_apply_kernel(float* __restrict__ out) {
    const int idx   = blockIdx.x * blockDim.x + threadIdx.x;
    const int h     = idx & (NH - 1);
    const int chunk = (idx >> 9) & (NC - 1);
    const int b     = idx >> 14;

    const float* gp = g_gates + ((size_t)b * NT + (size_t)chunk * CT) * G3 + h;
    float* Cp  = out + ((size_t)b * NT + (size_t)chunk * CT) * NH + h;
    float* OCp = Cp + (size_t)NB * NT * NH;

    float c = g_cin[((size_t)b * NC + chunk) * NH + h];
#pragma unroll 8
    for (int t = 0; t < CT; t++) {
        const float* gt = gp + (size_t)t * G3;
        const float z = gt[0];
        const float f = gt[NH];
        const float o = gt[2 * NH];
        c = f * c + (1.f - f) * z;
        Cp[(size_t)t * NH]  = c;
        OCp[(size_t)t * NH] = o * c;
    }
}

// ---------------------------------------------------------------------------
extern "C" void kernel_launch(void* const* d_in, const int* in_sizes, int n_in,
                              void* d_out, int out_size) {
    const float* x    = (const float*)d_in[0];   // [B, T, D]
    const float* w    = (const float*)d_in[1];   // [3H, D, 2]
    const float* bias = (const float*)d_in[2];   // [3H]
    float* out = (float*)d_out;                  // C then O*C

    const int padN = NB * (NT + 1) * (ND / 2);
    pad_x_kernel<<<(padN + 255) / 256, 256>>>(x);                  // launch 1

    dim3 tg(KD / 32, G3 / 32);
    transpose_wk_kernel<<<tg, dim3(32, 8)>>>(w);                   // launch 2

    bias_copy_kernel<<<G3 / 256, 256>>>(bias);                     // launch 3 (tiny)

    cudaFuncSetAttribute(gemm_mma_kernel,
                         cudaFuncAttributeMaxDynamicSharedMemorySize, SMEM_TOTAL);
    dim3 grid(G3 / BN, (NB * NT) / BM);          // (12, 256)
    gemm_mma_kernel<<<grid, 256, SMEM_TOTAL>>>();                  // launch 4 <- ncu

    fo_carry_kernel<<<(NB * NC * NH) / 256, 256>>>();
    fo_carry_scan_kernel<<<(NB * NH) / 256, 256>>>();
    fo_apply_kernel<<<(NB * NC * NH) / 256, 256>>>(out);
}

// round 16
// speedup vs baseline: 1.2410x; 1.0351x over previous
#include <cuda_runtime.h>
#include <cstdint>

#define NB 16
#define NT 2048
#define ND 512
#define NH 512
#define G3 1536
#define KD 1024

#define BM 128
#define BN 128
#define BK 32
#define KITER (KD / BK)      // 32
#define NSTAGE 3

// A: row-major [BM][PKA], k-pair interleaved columns; pitch 40 floats ->
//    LDS.64 banks (8g+2tig) mod 32 distinct per 16-lane phase.
#define PKA 40
#define A_EL (BM * PKA)          // 5120 floats
#define A_BYTES (A_EL * 4)       // 20480
// B: per chunk 4 k8-groups x 4 pair-rows x 264 floats (256 data + 8 pad)
#define PNB 264
#define B_EL (16 * PNB)          // 4224 floats
#define B_BYTES (B_EL * 4)       // 16896
#define B_OFF   (NSTAGE * A_BYTES)                 // 61440
#define SMEM_TOTAL (NSTAGE * (A_BYTES + B_BYTES))  // 112128 (x2 = 219KB)

#define NC 32
#define CT (NT / NC)         // 64

// Scratch (__device__ globals; no allocation allowed)
__device__ float g_xp[(size_t)NB * (NT + 1) * ND];   // tf32, padded, k-pair-interleaved cols
__device__ float g_Wk[(size_t)KD * G3];              // tf32 W, [group][pair][n][2] layout
__device__ float g_bias[G3];
__device__ float g_gates[(size_t)NB * NT * G3];      // post-activation gates
__device__ float g_carryA[(size_t)NB * NC * NH];
__device__ float g_carryB[(size_t)NB * NC * NH];
__device__ float g_cin[(size_t)NB * NC * NH];

// ---------------------------------------------------------------------------
__device__ __forceinline__ uint32_t s2u(const void* p) {
    uint32_t a;
    asm("{ .reg .u64 t; cvta.to.shared.u64 t, %1; cvt.u32.u64 %0, t; }"
        : "=r"(a) : "l"(p));
    return a;
}
__device__ __forceinline__ void cp16(uint32_t dst, const void* src) {
    asm volatile("cp.async.cg.shared.global [%0], [%1], 16;" :: "r"(dst), "l"(src));
}
__device__ __forceinline__ float tf32r(float v) {
    uint32_t o;
    asm("cvt.rna.tf32.f32 %0, %1;" : "=r"(o) : "f"(v));
    return __uint_as_float(o);
}
__device__ __forceinline__ void lds64(uint32_t& r0, uint32_t& r1, uint32_t a) {
    asm volatile("ld.shared.v2.b32 {%0, %1}, [%2];" : "=r"(r0), "=r"(r1) : "r"(a));
}
__device__ __forceinline__ void mma_tf32(float* c, const uint32_t* a,
                                         const uint32_t* b) {
    asm volatile(
        "mma.sync.aligned.m16n8k8.row.col.f32.tf32.tf32.f32 "
        "{%0,%1,%2,%3}, {%4,%5,%6,%7}, {%8,%9}, {%0,%1,%2,%3};"
        : "+f"(c[0]), "+f"(c[1]), "+f"(c[2]), "+f"(c[3])
        : "r"(a[0]), "r"(a[1]), "r"(a[2]), "r"(a[3]), "r"(b[0]), "r"(b[1]));
}

// ---------------------------------------------------------------------------
// Prep kernels
// ---------------------------------------------------------------------------
// g_xp[b][0]=0; g_xp[b][tt] = tf32(x[b][tt-1]) with columns pair-interleaved
// within each 8-group: out float2 at col 8*gb+2i holds (src col 8gb+i, 8gb+i+4).
__global__ void pad_x_kernel(const float* __restrict__ x) {
    const int PPB = (NT + 1) * (ND / 2);     // float2 per batch
    int idx = blockIdx.x * blockDim.x + threadIdx.x;
    if (idx >= NB * PPB) return;
    int b  = idx / PPB;
    int r  = idx - b * PPB;
    int tt = r / (ND / 2);
    int p  = r - tt * (ND / 2);              // 0..255
    int gb = p >> 2, i = p & 3;
    float2 v = make_float2(0.f, 0.f);
    if (tt > 0) {
        const float* src = x + ((size_t)b * NT + (tt - 1)) * ND + gb * 8 + i;
        v.x = tf32r(src[0]);
        v.y = tf32r(src[4]);
    }
    *reinterpret_cast<float2*>(
        g_xp + ((size_t)b * (NT + 1) + tt) * ND + gb * 8 + 2 * i) = v;
}

// g_Wk layout: [kgroup(128)][pair(4)][n(G3)][sub(2)], where kk = 8*kgroup + pair
// (sub=0) or + pair + 4 (sub=1). Same k-pair interleave as A.
__global__ void transpose_wk_kernel(const float* __restrict__ w) {
    __shared__ float tile[32][33];
    const int kk0 = blockIdx.x * 32;
    const int n0  = blockIdx.y * 32;
    const int tx = threadIdx.x, ty = threadIdx.y;   // (32, 8)
    const int ki = kk0 >> 9;
#pragma unroll
    for (int r = 0; r < 4; r++) {
        const int n  = n0 + ty + r * 8;
        const int d  = (kk0 + tx) & 511;
        tile[ty + r * 8][tx] = w[(size_t)n * KD + d * 2 + ki];
    }
    __syncthreads();
#pragma unroll
    for (int r = 0; r < 4; r++) {
        const int kk = kk0 + ty + r * 8;
        const int n  = n0 + tx;
        const size_t dst =
            (((size_t)((kk >> 3) * 4 + (kk & 3)) * G3) + n) * 2 + ((kk >> 2) & 1);
        g_Wk[dst] = tf32r(tile[tx][ty + r * 8]);
    }
}

// Launch #3 (tiny): positions the GEMM as the 4th launch for ncu capture.
__global__ void bias_copy_kernel(const float* __restrict__ bias) {
    int i = blockIdx.x * blockDim.x + threadIdx.x;
    if (i < G3) g_bias[i] = bias[i];
}

// ---------------------------------------------------------------------------
// tf32 mma.sync GEMM. CTA 128x128, 8 warps 2(M)x4(N), warp tile 64x32, BK=32,
// 3-stage cp.async. Mainloop unrolled by NSTAGE so EVERY smem address is
// base-register + compile-time immediate; global sources are two pointers
// advanced by a fixed stride per chunk (A operand is contiguous in k).
// ---------------------------------------------------------------------------
// Body for chunk with stage S (compile-time); loads next+2 chunk into stage S2.
#define GBODY(S, S2, DOLOAD)                                                    \
    do {                                                                        \
        asm volatile("cp.async.wait_group 1;");                                 \
        __syncthreads();                                                        \
        _Pragma("unroll")                                                       \
        for (int i = 0; i < 4; i++) {                                           \
            lds64(af[0][i][0], af[0][i][2],                                     \
                  aF + (S) * A_BYTES + i * (16 * PKA * 4));                     \
            lds64(af[0][i][1], af[0][i][3],                                     \
                  aF + (S) * A_BYTES + i * (16 * PKA * 4) + 8 * PKA * 4);       \
        }                                                                       \
        _Pragma("unroll")                                                       \
        for (int j = 0; j < 4; j++)                                             \
            lds64(bf[0][j][0], bf[0][j][1], bF + (S) * B_BYTES + j * 64);       \
        if (DOLOAD) {                                                           \
            _Pragma("unroll")                                                   \
            for (int i = 0; i < 4; i++)                                         \
                cp16(aDst + (S2) * A_BYTES + i * (32 * PKA * 4),                \
                     aload + i * (32 * ND));                                    \
            _Pragma("unroll")                                                   \
            for (int i = 0; i < 4; i++)                                         \
                cp16(bDst + (S2) * B_BYTES + i * (4 * PNB * 4),                 \
                     bload + i * (4 * G3 * 2));                                 \
            aload += 32;                                                        \
            bload += 16 * G3 * 2;                                               \
        }                                                                       \
        asm volatile("cp.async.commit_group;");                                 \
        _Pragma("unroll")                                                       \
        for (int k8 = 0; k8 < 4; k8++) {                                        \
            const int cur = k8 & 1, nxt = cur ^ 1;                              \
            if (k8 < 3) {                                                       \
                _Pragma("unroll")                                               \
                for (int i = 0; i < 4; i++) {                                   \
                    lds64(af[nxt][i][0], af[nxt][i][2],                         \
                          aF + (S) * A_BYTES + i * (16 * PKA * 4) +             \
                              (k8 + 1) * 32);                                   \
                    lds64(af[nxt][i][1], af[nxt][i][3],                         \
                          aF + (S) * A_BYTES + i * (16 * PKA * 4) +             \
                              8 * PKA * 4 + (k8 + 1) * 32);                     \
                }                                                               \
                _Pragma("unroll")                                               \
                for (int j = 0; j < 4; j++)                                     \
                    lds64(bf[nxt][j][0], bf[nxt][j][1],                         \
                          bF + (S) * B_BYTES + (k8 + 1) * (4 * PNB * 4) +       \
                              j * 64);                                          \
            }                                                                   \
            _Pragma("unroll")                                                   \
            for (int i = 0; i < 4; i++)                                         \
                _Pragma("unroll")                                               \
                for (int j = 0; j < 4; j++)                                     \
                    mma_tf32(cf[i][j], af[cur][i], bf[cur][j]);                 \
        }                                                                       \
    } while (0)

__global__ __launch_bounds__(256, 2)
void gemm_mma_kernel() {
    extern __shared__ float sm[];
    const uint32_t sb = s2u(sm);
    const int tid = threadIdx.x;
    const int wid = tid >> 5, lid = tid & 31;
    const int wm = wid & 1, wn = wid >> 1;
    const int g = lid >> 2, tig = lid & 3;

    const int n0 = blockIdx.x * BN;
    const int m0 = blockIdx.y * BM;
    const int b  = m0 >> 11;
    const int t0 = m0 & (NT - 1);

    // invariant base addresses (everything else is an immediate)
    const uint32_t aF   = sb + ((wm * 64 + g) * PKA + 2 * tig) * 4;
    const uint32_t bF   = sb + B_OFF + (tig * PNB + (wn * 32 + g) * 2) * 4;
    const uint32_t aDst = sb + (((tid >> 3) * PKA + (tid & 7) * 4)) * 4;
    const uint32_t bDst = sb + B_OFF + (((tid >> 6) * PNB + (tid & 63) * 4)) * 4;

    // global sources: advance by one chunk stride per body.
    // A rows are contiguous in k (row m = [xp[t]|xp[t+1]]) -> +32 floats/chunk.
    const float* aload = g_xp +
        ((size_t)(b * (NT + 1) + t0) + (tid >> 3)) * ND + (tid & 7) * 4;
    const float* bload = g_Wk +
        (size_t)(tid >> 6) * (G3 * 2) + n0 * 2 + (tid & 63) * 4;

    float cf[4][4][4];
#pragma unroll
    for (int i = 0; i < 4; i++)
#pragma unroll
        for (int j = 0; j < 4; j++)
#pragma unroll
            for (int q = 0; q < 4; q++) cf[i][j][q] = 0.f;

    uint32_t af[2][4][4], bf[2][4][2];

    // Prologue: chunk 0 -> stage 0, chunk 1 -> stage 1
#pragma unroll
    for (int i = 0; i < 4; i++)
        cp16(aDst + i * (32 * PKA * 4), aload + i * (32 * ND));
#pragma unroll
    for (int i = 0; i < 4; i++)
        cp16(bDst + i * (4 * PNB * 4), bload + i * (4 * G3 * 2));
    asm volatile("cp.async.commit_group;");
#pragma unroll
    for (int i = 0; i < 4; i++)
        cp16(aDst + A_BYTES + i * (32 * PKA * 4), aload + 32 + i * (32 * ND));
#pragma unroll
    for (int i = 0; i < 4; i++)
        cp16(bDst + B_BYTES + i * (4 * PNB * 4),
             bload + 16 * G3 * 2 + i * (4 * G3 * 2));
    asm volatile("cp.async.commit_group;");
    aload += 64;                 // now at chunk 2
    bload += 32 * G3 * 2;

    // Mainloop: 10 triples (chunks 0..29), then peel chunks 30, 31.
    for (int c0 = 0; c0 < 30; c0 += 3) {
        GBODY(0, 2, true);
        GBODY(1, 0, true);
        GBODY(2, 1, true);
    }
    GBODY(0, 2, false);
    GBODY(1, 0, false);

    // Epilogue: bias + activation, direct store to g_gates.
#pragma unroll
    for (int j = 0; j < 4; j++) {
        const int col = n0 + wn * 32 + j * 8 + 2 * tig;
        const float b0 = g_bias[col], b1 = g_bias[col + 1];
        const bool is_z = col < NH;
#pragma unroll
        for (int i = 0; i < 4; i++) {
            const int r0 = m0 + wm * 64 + i * 16 + g;
#pragma unroll
            for (int h = 0; h < 2; h++) {
                float v0 = cf[i][j][2 * h]     + b0;
                float v1 = cf[i][j][2 * h + 1] + b1;
                float o0, o1;
                if (is_z) {
                    float e0 = __expf(2.f * v0), e1 = __expf(2.f * v1);
                    o0 = 1.f - __fdividef(2.f, e0 + 1.f);
                    o1 = 1.f - __fdividef(2.f, e1 + 1.f);
                } else {
                    o0 = __fdividef(1.f, 1.f + __expf(-v0));
                    o1 = __fdividef(1.f, 1.f + __expf(-v1));
                }
                *reinterpret_cast<float2*>(
                    g_gates + (size_t)(r0 + 8 * h) * G3 + col) =
                    make_float2(o0, o1);
            }
        }
    }
}

// ---------------------------------------------------------------------------
// fo-pool: chunked linear-recurrence scan. NC=32 chunks -> 262k threads.
// ---------------------------------------------------------------------------
__global__ __launch_bounds__(256)
void fo_carry_kernel() {
    const int idx   = blockIdx.x * blockDim.x + threadIdx.x;
    const int h     = idx & (NH - 1);
    const int chunk = (idx >> 9) & (NC - 1);
    const int b     = idx >> 14;

    const float* gp = g_gates + ((size_t)b * NT + (size_t)chunk * CT) * G3 + h;
    float A = 1.f, Bc = 0.f;
#pragma unroll 8
    for (int t = 0; t < CT; t++) {
        const float* gt = gp + (size_t)t * G3;
        const float z = gt[0];
        const float f = gt[NH];
        Bc = f * Bc + (1.f - f) * z;
        A *= f;
    }
    const size_t ci = ((size_t)b * NC + chunk) * NH + h;
    g_carryA[ci] = A;
    g_carryB[ci] = Bc;
}

__global__ __launch_bounds__(256)
void fo_carry_scan_kernel() {
    const int idx = blockIdx.x * blockDim.x + threadIdx.x;
    const int h = idx & (NH - 1);
    const int b = idx >> 9;
    float c = 0.f;
#pragma unroll
    for (int j = 0; j < NC; j++) {
        const size_t ci = ((size_t)b * NC + j) * NH + h;
        g_cin[ci] = c;
        c = g_carryA[ci] * c + g_carryB[ci];
    }
}

__global__ __launch_bounds__(256)
void fo_apply_kernel(float* __restrict__ out) {
    const int idx   = blockIdx.x * blockDim.x + threadIdx.x;
    const int h     = idx & (NH - 1);
    const int chunk = (idx >> 9) & (NC - 1);
    const int b     = idx >> 14;

    const float* gp = g_gates + ((size_t)b * NT + (size_t)chunk * CT) * G3 + h;
    float* Cp  = out + ((size_t)b * NT + (size_t)chunk * CT) * NH + h;
    float* OCp = Cp + (size_t)NB * NT * NH;

    float c = g_cin[((size_t)b * NC + chunk) * NH + h];
#pragma unroll 8
    for (int t = 0; t < CT; t++) {
        const float* gt = gp + (size_t)t * G3;
        const float z = gt[0];
        const float f = gt[NH];
        const float o = gt[2 * NH];
        c = f * c + (1.f - f) * z;
        Cp[(size_t)t * NH]  = c;
        OCp[(size_t)t * NH] = o * c;
    }
}

// ---------------------------------------------------------------------------
extern "C" void kernel_launch(void* const* d_in, const int* in_sizes, int n_in,
                              void* d_out, int out_size) {
    const float* x    = (const float*)d_in[0];   // [B, T, D]
    const float* w    = (const float*)d_in[1];   // [3H, D, 2]
    const float* bias = (const float*)d_in[2];   // [3H]
    float* out = (float*)d_out;                  // C then O*C

    const int padN = NB * (NT + 1) * (ND / 2);
    pad_x_kernel<<<(padN + 255) / 256, 256>>>(x);                  // launch 1

    dim3 tg(KD / 32, G3 / 32);
    transpose_wk_kernel<<<tg, dim3(32, 8)>>>(w);                   // launch 2

    bias_copy_kernel<<<G3 / 256, 256>>>(bias);                     // launch 3 (tiny)

    cudaFuncSetAttribute(gemm_mma_kernel,
                         cudaFuncAttributeMaxDynamicSharedMemorySize, SMEM_TOTAL);
    dim3 grid(G3 / BN, (NB * NT) / BM);          // (12, 256)
    gemm_mma_kernel<<<grid, 256, SMEM_TOTAL>>>();                  // launch 4 <- ncu

    fo_carry_kernel<<<(NB * NC * NH) / 256, 256>>>();
    fo_carry_scan_kernel<<<(NB * NH) / 256, 256>>>();
    fo_apply_kernel<<<(NB * NC * NH) / 256, 256>>>(out);
}